// round 12
// baseline (speedup 1.0000x reference)
#include <cuda_runtime.h>
#include <cuda_fp16.h>
#include <cstdint>

#define B_N 1024
#define D_N 512
#define C_N 100000
#define MARGIN 0.1f
#define EPSV 1e-8f
#define XSCL 16.0f                   // fp8 pre-scale for normalized X
#define FXS 256.0f                   // fixed-point scale for deterministic finish

#define NT 128                       // classes per CTA tile
#define NTILES 782
#define NMB 8                        // 1024/128 row blocks
#define NKC 4                        // 512/128 k-chunks per m-block
#define NSTEP (NMB * NKC)            // 32
#define ES_STRB 528                  // E smem row stride bytes (512 fp8 + 16 pad)
#define XR_BYTES 144                 // X chunk row stride bytes (128 fp8 + 16 pad)

#define XC_OFF (NT * ES_STRB)        // 67584
#define XC_BYTES (128 * XR_BYTES)    // 18432
#define NBUF 2
#define INVN_OFF (XC_OFF + NBUF * XC_BYTES)  // 104448
#define VM_OFF (INVN_OFF + 512)
#define SMEM_BYTES (VM_OFF + 512)            // 105472 -> 2 CTAs/SM

__device__ __align__(128) unsigned char g_Xq[B_N * D_N]; // fp8 e4m3, x_n * 16
__device__ float g_t[B_N];
__device__ long long g_acc;
__device__ unsigned int g_done;

// ---------------------------------------------------------------------------
__device__ __forceinline__ uint32_t smem_u32(const void* p) {
    uint32_t a;
    asm("{ .reg .u64 t; cvta.to.shared.u64 t, %1; cvt.u32.u64 %0, t; }" : "=r"(a) : "l"(p));
    return a;
}
__device__ __forceinline__ void cp16(uint32_t dst, const void* src) {
    asm volatile("cp.async.cg.shared.global [%0], [%1], 16;" :: "r"(dst), "l"(src));
}
__device__ __forceinline__ void ldsm4(uint32_t* r, uint32_t a) {
    asm volatile("ldmatrix.sync.aligned.m8n8.x4.shared.b16 {%0,%1,%2,%3}, [%4];"
                 : "=r"(r[0]), "=r"(r[1]), "=r"(r[2]), "=r"(r[3]) : "r"(a));
}
__device__ __forceinline__ uint32_t f4_to_e4m3x4(float x, float y, float z, float w) {
    uint32_t pk;
    asm("{ .reg .b16 lo, hi;\n"
        "cvt.rn.satfinite.e4m3x2.f32 lo, %2, %1;\n"
        "cvt.rn.satfinite.e4m3x2.f32 hi, %4, %3;\n"
        "mov.b32 %0, {lo, hi}; }"
        : "=r"(pk) : "f"(x), "f"(y), "f"(z), "f"(w));
    return pk;
}

// ---------------------------------------------------------------------------
// Kernel 1 (fused): X normalize -> fp8, fp32-exact target cosine, acc reset
// ---------------------------------------------------------------------------
__global__ void k_prep(const float* __restrict__ X, const float* __restrict__ E,
                       const int* __restrict__ T) {
    int b = blockIdx.x;
    int t = threadIdx.x; // 128 threads, 4 floats each
    if (b == 0 && t == 0) { g_acc = 0LL; g_done = 0u; }
    int tg = max(0, min(T[b], C_N - 1));
    float4 v = *(const float4*)(X + (size_t)b * D_N + 4 * t);
    float4 e = *(const float4*)(E + (size_t)tg * D_N + 4 * t);
    float ss = v.x * v.x + v.y * v.y + v.z * v.z + v.w * v.w;
    float se = e.x * e.x + e.y * e.y + e.z * e.z + e.w * e.w;
    float sx = v.x * e.x + v.y * e.y + v.z * e.z + v.w * e.w;
    __shared__ float s1[128], s2[128], s3[128];
    s1[t] = ss; s2[t] = se; s3[t] = sx;
    __syncthreads();
    for (int s = 64; s > 0; s >>= 1) {
        if (t < s) { s1[t] += s1[t + s]; s2[t] += s2[t + s]; s3[t] += s3[t + s]; }
        __syncthreads();
    }
    float inv = 1.0f / fmaxf(sqrtf(s1[0]), EPSV);
    float q = inv * XSCL;
    *(uint32_t*)(g_Xq + (size_t)b * D_N + 4 * t) =
        f4_to_e4m3x4(v.x * q, v.y * q, v.z * q, v.w * q);
    if (t == 0)
        g_t[b] = s3[0] * inv / fmaxf(sqrtf(s2[0]), EPSV);
}

// ---------------------------------------------------------------------------
// Kernel 2: fp8 m16n8k32 (f16 acc), 128-k chunks, half2 hinge epilogue,
// deterministic fixed-point atomic finish.
// ---------------------------------------------------------------------------
__global__ __launch_bounds__(256, 2) void k_main(const float* __restrict__ E,
                                                 float* __restrict__ out) {
    extern __shared__ __align__(1024) unsigned char smem[];
    uint32_t sbase = smem_u32(smem);
    float* invn = (float*)(smem + INVN_OFF);
    float* vmsk = (float*)(smem + VM_OFF);
    int tid = threadIdx.x, lane = tid & 31, wid = tid >> 5;
    int warp_m = wid >> 2;  // 0..1 -> 64 rows
    int warp_n = wid & 3;   // 0..3 -> 32 classes
    int c0 = blockIdx.x * NT;

    // ---- Phase 1: E tile fp32->e4m3 + inv-norms (/16 folded) + validity ----
    {
        int cl = tid >> 1, pr = tid & 1;
        int gc = c0 + cl;
        bool vld = gc < C_N;
        const float4* src = (const float4*)(E + (size_t)(vld ? gc : 0) * D_N);
        float ss = 0.f;
#pragma unroll 8
        for (int i = 0; i < 64; i++) {
            int f4 = pr + 2 * i;
            float4 v = vld ? src[f4] : make_float4(0.f, 0.f, 0.f, 0.f);
            ss += v.x * v.x + v.y * v.y + v.z * v.z + v.w * v.w;
            *(uint32_t*)(smem + cl * ES_STRB + f4 * 4) =
                f4_to_e4m3x4(v.x, v.y, v.z, v.w);
        }
        ss += __shfl_xor_sync(0xffffffffu, ss, 1);
        if (pr == 0) {
            invn[cl] = vld ? (1.0f / (fmaxf(sqrtf(ss), EPSV) * XSCL)) : 0.f;
            vmsk[cl] = vld ? 1.f : 0.f;
        }
    }
    __syncthreads();

    // per-thread epilogue constants in half2 (built once per tile)
    __half2 iv2[4], vm2[4];
#pragma unroll
    for (int in = 0; in < 4; in++) {
        int c = warp_n * 32 + in * 8 + (lane & 3) * 2;
        iv2[in] = __floats2half2_rn(invn[c], invn[c + 1]);
        vm2[in] = __floats2half2_rn(vmsk[c], vmsk[c + 1]);
    }
    const __half2 hz = __floats2half2_rn(0.f, 0.f);

    // ---- fragment addresses (relative, bytes) ----
    uint32_t aRow[4];
#pragma unroll
    for (int im = 0; im < 4; im++)
        aRow[im] = (uint32_t)((warp_m * 64 + im * 16 + (lane & 15)) * XR_BYTES +
                              (lane >> 4) * 16);
    uint32_t bRow[2];
#pragma unroll
    for (int g = 0; g < 2; g++)
        bRow[g] = (uint32_t)((warp_n * 32 + g * 16 + (lane & 15)) * ES_STRB +
                             (lane >> 4) * 16);

    // stage one 128-row x 128-k chunk (18KB)
    auto stage = [&](int s, int buf) {
        int mb = s >> 2, kc = s & 3;
        const char* src = (const char*)g_Xq + (size_t)mb * 128 * 512 + kc * 128;
        uint32_t dst = sbase + XC_OFF + buf * XC_BYTES;
#pragma unroll
        for (int j = 0; j < 4; j++) {
            int i = tid + j * 256;
            int row = i >> 3, seg = i & 7;
            cp16(dst + row * XR_BYTES + seg * 16, src + (size_t)row * 512 + seg * 16);
        }
        asm volatile("cp.async.commit_group;" ::: "memory");
    };

    uint32_t acc[4][4][2]; // f16x2 accumulators
#pragma unroll
    for (int im = 0; im < 4; im++)
#pragma unroll
        for (int in = 0; in < 4; in++) {
            acc[im][in][0] = 0u;
            acc[im][in][1] = 0u;
        }
    float local = 0.f;

    stage(0, 0);

    for (int step = 0; step < NSTEP; step++) {
        asm volatile("cp.async.wait_group 0;" ::: "memory");
        __syncthreads();
        if (step + 1 < NSTEP) stage(step + 1, (step + 1) & 1);

        int kc = step & 3;
        uint32_t abase = sbase + XC_OFF + (step & 1) * XC_BYTES;
        uint32_t bko = sbase + (uint32_t)(kc * 128);

#pragma unroll
        for (int ks = 0; ks < 4; ks++) {  // four k32 steps per 128-k chunk
            uint32_t a[4][4], bb[2][4];
#pragma unroll
            for (int im = 0; im < 4; im++) ldsm4(a[im], abase + aRow[im] + ks * 32);
#pragma unroll
            for (int g = 0; g < 2; g++) ldsm4(bb[g], bko + bRow[g] + ks * 32);
#pragma unroll
            for (int im = 0; im < 4; im++)
#pragma unroll
                for (int in = 0; in < 4; in++)
                    asm volatile(
                        "mma.sync.aligned.m16n8k32.row.col.f16.e4m3.e4m3.f16 "
                        "{%0,%1}, {%2,%3,%4,%5}, {%6,%7}, {%0,%1};"
                        : "+r"(acc[im][in][0]), "+r"(acc[im][in][1])
                        : "r"(a[im][0]), "r"(a[im][1]), "r"(a[im][2]), "r"(a[im][3]),
                          "r"(bb[in >> 1][in & 1]), "r"(bb[in >> 1][(in & 1) + 2]));
        }

        // ---- m-block epilogue (half2 hinge) ----
        if (kc == 3) {
            int mb = step >> 2;
            int rbase = mb * 128 + warp_m * 64 + (lane >> 2);
#pragma unroll
            for (int im = 0; im < 4; im++) {
                __half2 hb0 = __float2half2_rn(MARGIN - g_t[rbase + im * 16]);
                __half2 hb1 = __float2half2_rn(MARGIN - g_t[rbase + im * 16 + 8]);
                __half2 s0 = hz, s1 = hz;
#pragma unroll
                for (int in = 0; in < 4; in++) {
                    __half2 h01 = *(__half2*)&acc[im][in][0];
                    __half2 h23 = *(__half2*)&acc[im][in][1];
                    __half2 t0 = __hmax2(__hfma2(h01, iv2[in], hb0), hz);
                    __half2 t1 = __hmax2(__hfma2(h23, iv2[in], hb1), hz);
                    s0 = __hadd2(s0, __hmul2(t0, vm2[in]));
                    s1 = __hadd2(s1, __hmul2(t1, vm2[in]));
                    acc[im][in][0] = 0u;
                    acc[im][in][1] = 0u;
                }
                float2 f0 = __half22float2(s0);
                float2 f1 = __half22float2(s1);
                local += (f0.x + f0.y) + (f1.x + f1.y);
            }
        }
    }

    // ---- CTA reduction + deterministic fixed-point global accumulation ----
#pragma unroll
    for (int off = 16; off > 0; off >>= 1)
        local += __shfl_xor_sync(0xffffffffu, local, off);
    __shared__ float red[8];
    if (lane == 0) red[wid] = local;
    __syncthreads();
    if (tid == 0) {
        float s = 0.f;
#pragma unroll
        for (int w = 0; w < 8; w++) s += red[w];
        atomicAdd((unsigned long long*)&g_acc,
                  (unsigned long long)(long long)llrintf(s * FXS));
        __threadfence();
        unsigned int prev = atomicAdd(&g_done, 1u);
        if (prev == NTILES - 1) {
            long long total = (long long)atomicAdd((unsigned long long*)&g_acc, 0ULL);
            out[0] = (float)((double)total / (double)FXS / (double)B_N - (double)MARGIN);
        }
    }
}

// ---------------------------------------------------------------------------
extern "C" void kernel_launch(void* const* d_in, const int* in_sizes, int n_in,
                              void* d_out, int out_size) {
    const float* X = (const float*)d_in[0];   // [1024, 512] fp32
    const float* E = (const float*)d_in[1];   // [100000, 512] fp32
    const int* T = (const int*)d_in[2];       // [1024] int32
    float* out = (float*)d_out;

    cudaFuncSetAttribute(k_main, cudaFuncAttributeMaxDynamicSharedMemorySize,
                         SMEM_BYTES);

    k_prep<<<B_N, 128>>>(X, E, T);
    k_main<<<NTILES, 256, SMEM_BYTES>>>(E, out);
}

// round 13
// speedup vs baseline: 1.0568x; 1.0568x over previous
#include <cuda_runtime.h>
#include <cuda_fp16.h>
#include <cstdint>

#define B_N 1024
#define D_N 512
#define C_N 100000
#define MARGIN 0.1f
#define EPSV 1e-8f
#define XSCL 16.0f                   // fp8 pre-scale for normalized X
#define FXS 256.0f                   // fixed-point scale for deterministic finish

#define NT 128                       // classes per CTA tile
#define NTILES 782
#define NMB 8                        // 1024/128 row blocks
#define NKC 8                        // 512/64 k-chunks per m-block
#define NSTEP (NMB * NKC)
#define ES_STRB 528                  // E smem row stride bytes (512 fp8 + 16 pad)
#define XR_BYTES 80                  // X chunk row stride bytes (64 fp8 + 16 pad)

#define XC_OFF (NT * ES_STRB)        // 67584
#define XC_BYTES (128 * XR_BYTES)    // 10240
#define NBUF 4
#define INVN_OFF (XC_OFF + NBUF * XC_BYTES)  // 108544
#define VM_OFF (INVN_OFF + 512)
#define SMEM_BYTES (VM_OFF + 512)            // 109568 -> 2 CTAs/SM

__device__ __align__(128) unsigned char g_Xq[B_N * D_N]; // fp8 e4m3, x_n * 16
__device__ float g_t[B_N];
__device__ long long g_acc;
__device__ unsigned int g_done;

// ---------------------------------------------------------------------------
__device__ __forceinline__ uint32_t smem_u32(const void* p) {
    uint32_t a;
    asm("{ .reg .u64 t; cvta.to.shared.u64 t, %1; cvt.u32.u64 %0, t; }" : "=r"(a) : "l"(p));
    return a;
}
__device__ __forceinline__ void cp16(uint32_t dst, const void* src) {
    asm volatile("cp.async.cg.shared.global [%0], [%1], 16;" :: "r"(dst), "l"(src));
}
__device__ __forceinline__ void ldsm4(uint32_t* r, uint32_t a) {
    asm volatile("ldmatrix.sync.aligned.m8n8.x4.shared.b16 {%0,%1,%2,%3}, [%4];"
                 : "=r"(r[0]), "=r"(r[1]), "=r"(r[2]), "=r"(r[3]) : "r"(a));
}
__device__ __forceinline__ uint32_t f4_to_e4m3x4(float x, float y, float z, float w) {
    uint32_t pk;
    asm("{ .reg .b16 lo, hi;\n"
        "cvt.rn.satfinite.e4m3x2.f32 lo, %2, %1;\n"
        "cvt.rn.satfinite.e4m3x2.f32 hi, %4, %3;\n"
        "mov.b32 %0, {lo, hi}; }"
        : "=r"(pk) : "f"(x), "f"(y), "f"(z), "f"(w));
    return pk;
}

// ---------------------------------------------------------------------------
// Kernel 1 (fused): X normalize -> fp8, fp32-exact target cosine, acc reset
// ---------------------------------------------------------------------------
__global__ void k_prep(const float* __restrict__ X, const float* __restrict__ E,
                       const int* __restrict__ T) {
    int b = blockIdx.x;
    int t = threadIdx.x; // 128 threads, 4 floats each
    if (b == 0 && t == 0) { g_acc = 0LL; g_done = 0u; }
    int tg = max(0, min(T[b], C_N - 1));
    float4 v = *(const float4*)(X + (size_t)b * D_N + 4 * t);
    float4 e = *(const float4*)(E + (size_t)tg * D_N + 4 * t);
    float ss = v.x * v.x + v.y * v.y + v.z * v.z + v.w * v.w;
    float se = e.x * e.x + e.y * e.y + e.z * e.z + e.w * e.w;
    float sx = v.x * e.x + v.y * e.y + v.z * e.z + v.w * e.w;
    __shared__ float s1[128], s2[128], s3[128];
    s1[t] = ss; s2[t] = se; s3[t] = sx;
    __syncthreads();
    for (int s = 64; s > 0; s >>= 1) {
        if (t < s) { s1[t] += s1[t + s]; s2[t] += s2[t + s]; s3[t] += s3[t + s]; }
        __syncthreads();
    }
    float inv = 1.0f / fmaxf(sqrtf(s1[0]), EPSV);
    float q = inv * XSCL;
    *(uint32_t*)(g_Xq + (size_t)b * D_N + 4 * t) =
        f4_to_e4m3x4(v.x * q, v.y * q, v.z * q, v.w * q);
    if (t == 0)
        g_t[b] = s3[0] * inv / fmaxf(sqrtf(s2[0]), EPSV);
}

// ---------------------------------------------------------------------------
// Kernel 2: fp8 m16n8k32 mma.sync (f16 acc), 4-deep cp.async ring, half2
// hinge epilogue, deterministic fixed-point atomic finish.
// ---------------------------------------------------------------------------
__global__ __launch_bounds__(256, 2) void k_main(const float* __restrict__ E,
                                                 float* __restrict__ out) {
    extern __shared__ __align__(1024) unsigned char smem[];
    uint32_t sbase = smem_u32(smem);
    float* invn = (float*)(smem + INVN_OFF);
    float* vmsk = (float*)(smem + VM_OFF);
    int tid = threadIdx.x, lane = tid & 31, wid = tid >> 5;
    int warp_m = wid >> 2;  // 0..1 -> 64 rows
    int warp_n = wid & 3;   // 0..3 -> 32 classes
    int c0 = blockIdx.x * NT;

    // ---- Phase 1: E tile fp32->e4m3 + inv-norms (/16 folded) + validity ----
    {
        int cl = tid >> 1, pr = tid & 1;
        int gc = c0 + cl;
        bool vld = gc < C_N;
        const float4* src = (const float4*)(E + (size_t)(vld ? gc : 0) * D_N);
        float ss = 0.f;
#pragma unroll 8
        for (int i = 0; i < 64; i++) {
            int f4 = pr + 2 * i;
            float4 v = vld ? src[f4] : make_float4(0.f, 0.f, 0.f, 0.f);
            ss += v.x * v.x + v.y * v.y + v.z * v.z + v.w * v.w;
            *(uint32_t*)(smem + cl * ES_STRB + f4 * 4) =
                f4_to_e4m3x4(v.x, v.y, v.z, v.w);
        }
        ss += __shfl_xor_sync(0xffffffffu, ss, 1);
        if (pr == 0) {
            invn[cl] = vld ? (1.0f / (fmaxf(sqrtf(ss), EPSV) * XSCL)) : 0.f;
            vmsk[cl] = vld ? 1.f : 0.f;
        }
    }
    __syncthreads();

    // per-thread epilogue constants in half2 (built once per tile)
    __half2 iv2[4], vm2[4];
#pragma unroll
    for (int in = 0; in < 4; in++) {
        int c = warp_n * 32 + in * 8 + (lane & 3) * 2;
        iv2[in] = __floats2half2_rn(invn[c], invn[c + 1]);
        vm2[in] = __floats2half2_rn(vmsk[c], vmsk[c + 1]);
    }
    const __half2 hz = __floats2half2_rn(0.f, 0.f);

    // ---- fragment addresses (relative, bytes) ----
    uint32_t aRow[4];
#pragma unroll
    for (int im = 0; im < 4; im++)
        aRow[im] = (uint32_t)((warp_m * 64 + im * 16 + (lane & 15)) * XR_BYTES +
                              (lane >> 4) * 16);
    uint32_t bRow[2];
#pragma unroll
    for (int g = 0; g < 2; g++)
        bRow[g] = (uint32_t)((warp_n * 32 + g * 16 + (lane & 15)) * ES_STRB +
                             (lane >> 4) * 16);

    auto stage = [&](int s, int buf) {
        int mb = s >> 3, kc = s & 7;
        const char* src = (const char*)g_Xq + (size_t)mb * 128 * 512 + kc * 64;
        uint32_t dst = sbase + XC_OFF + buf * XC_BYTES;
#pragma unroll
        for (int j = 0; j < 2; j++) {
            int i = tid + j * 256;
            int row = i >> 2, seg = i & 3;
            cp16(dst + row * XR_BYTES + seg * 16, src + (size_t)row * 512 + seg * 16);
        }
        asm volatile("cp.async.commit_group;" ::: "memory");
    };

    uint32_t acc[4][4][2]; // f16x2 accumulators
#pragma unroll
    for (int im = 0; im < 4; im++)
#pragma unroll
        for (int in = 0; in < 4; in++) {
            acc[im][in][0] = 0u;
            acc[im][in][1] = 0u;
        }
    float local = 0.f;

    stage(0, 0);
    stage(1, 1);
    stage(2, 2);

    for (int step = 0; step < NSTEP; step++) {
        if (step >= NSTEP - 3)
            asm volatile("cp.async.wait_group 0;" ::: "memory");
        else
            asm volatile("cp.async.wait_group 2;" ::: "memory");
        __syncthreads();
        if (step < NSTEP - 3) stage(step + 3, (step + 3) & 3);

        int kc = step & 7;
        int buf = step & 3;
        uint32_t abase = sbase + XC_OFF + buf * XC_BYTES;
        uint32_t bko = sbase + (uint32_t)(kc * 64);

#pragma unroll
        for (int ks = 0; ks < 2; ks++) {  // two k32 steps per 64-k chunk
            uint32_t a[4][4], bb[2][4];
#pragma unroll
            for (int im = 0; im < 4; im++) ldsm4(a[im], abase + aRow[im] + ks * 32);
#pragma unroll
            for (int g = 0; g < 2; g++) ldsm4(bb[g], bko + bRow[g] + ks * 32);
#pragma unroll
            for (int im = 0; im < 4; im++)
#pragma unroll
                for (int in = 0; in < 4; in++)
                    asm volatile(
                        "mma.sync.aligned.m16n8k32.row.col.f16.e4m3.e4m3.f16 "
                        "{%0,%1}, {%2,%3,%4,%5}, {%6,%7}, {%0,%1};"
                        : "+r"(acc[im][in][0]), "+r"(acc[im][in][1])
                        : "r"(a[im][0]), "r"(a[im][1]), "r"(a[im][2]), "r"(a[im][3]),
                          "r"(bb[in >> 1][in & 1]), "r"(bb[in >> 1][(in & 1) + 2]));
        }

        // ---- m-block epilogue (half2 hinge) ----
        if (kc == 7) {
            int mb = step >> 3;
            int rbase = mb * 128 + warp_m * 64 + (lane >> 2);
#pragma unroll
            for (int im = 0; im < 4; im++) {
                __half2 hb0 = __float2half2_rn(MARGIN - g_t[rbase + im * 16]);
                __half2 hb1 = __float2half2_rn(MARGIN - g_t[rbase + im * 16 + 8]);
                __half2 s0 = hz, s1 = hz;
#pragma unroll
                for (int in = 0; in < 4; in++) {
                    __half2 h01 = *(__half2*)&acc[im][in][0];
                    __half2 h23 = *(__half2*)&acc[im][in][1];
                    __half2 t0 = __hmax2(__hfma2(h01, iv2[in], hb0), hz);
                    __half2 t1 = __hmax2(__hfma2(h23, iv2[in], hb1), hz);
                    s0 = __hadd2(s0, __hmul2(t0, vm2[in]));
                    s1 = __hadd2(s1, __hmul2(t1, vm2[in]));
                    acc[im][in][0] = 0u;
                    acc[im][in][1] = 0u;
                }
                float2 f0 = __half22float2(s0);
                float2 f1 = __half22float2(s1);
                local += (f0.x + f0.y) + (f1.x + f1.y);
            }
        }
    }

    // ---- CTA reduction + deterministic fixed-point global accumulation ----
#pragma unroll
    for (int off = 16; off > 0; off >>= 1)
        local += __shfl_xor_sync(0xffffffffu, local, off);
    __shared__ float red[8];
    if (lane == 0) red[wid] = local;
    __syncthreads();
    if (tid == 0) {
        float s = 0.f;
#pragma unroll
        for (int w = 0; w < 8; w++) s += red[w];
        atomicAdd((unsigned long long*)&g_acc,
                  (unsigned long long)(long long)llrintf(s * FXS));
        __threadfence();
        unsigned int prev = atomicAdd(&g_done, 1u);
        if (prev == NTILES - 1) {
            long long total = (long long)atomicAdd((unsigned long long*)&g_acc, 0ULL);
            out[0] = (float)((double)total / (double)FXS / (double)B_N - (double)MARGIN);
        }
    }
}

// ---------------------------------------------------------------------------
extern "C" void kernel_launch(void* const* d_in, const int* in_sizes, int n_in,
                              void* d_out, int out_size) {
    const float* X = (const float*)d_in[0];   // [1024, 512] fp32
    const float* E = (const float*)d_in[1];   // [100000, 512] fp32
    const int* T = (const int*)d_in[2];       // [1024] int32
    float* out = (float*)d_out;

    cudaFuncSetAttribute(k_main, cudaFuncAttributeMaxDynamicSharedMemorySize,
                         SMEM_BYTES);

    k_prep<<<B_N, 128>>>(X, E, T);
    k_main<<<NTILES, 256, SMEM_BYTES>>>(E, out);
}

// round 14
// speedup vs baseline: 1.1139x; 1.0541x over previous
#include <cuda_runtime.h>
#include <cuda_fp16.h>
#include <cstdint>

#define B_N 1024
#define D_N 512
#define C_N 100000
#define MARGIN 0.1f
#define EPSV 1e-8f
#define XSCL 16.0f                   // fp8 pre-scale for normalized X
#define FXS 256.0f                   // fixed-point scale for deterministic finish

#define NT 64                        // classes per CTA tile
#define NTILES 1563                  // ceil(100000/64)
#define NMB 8                        // 1024/128 row blocks
#define NKC 8                        // 512/64 k-chunks per m-block
#define NSTEP (NMB * NKC)
#define ES_STRB 528                  // E smem row stride bytes (512 fp8 + 16 pad)
#define XR_BYTES 80                  // X chunk row stride bytes (64 fp8 + 16 pad)

#define XC_OFF (NT * ES_STRB)        // 33792
#define XC_BYTES (128 * XR_BYTES)    // 10240
#define NBUF 4
#define INVN_OFF (XC_OFF + NBUF * XC_BYTES)  // 74752
#define VM_OFF (INVN_OFF + 256)
#define SMEM_BYTES (VM_OFF + 256)            // 75264 -> 3 CTAs/SM

__device__ __align__(128) unsigned char g_Xq[B_N * D_N]; // fp8 e4m3, x_n * 16
__device__ float g_t[B_N];
__device__ long long g_acc;
__device__ unsigned int g_done;

// ---------------------------------------------------------------------------
__device__ __forceinline__ uint32_t smem_u32(const void* p) {
    uint32_t a;
    asm("{ .reg .u64 t; cvta.to.shared.u64 t, %1; cvt.u32.u64 %0, t; }" : "=r"(a) : "l"(p));
    return a;
}
__device__ __forceinline__ void cp16(uint32_t dst, const void* src) {
    asm volatile("cp.async.cg.shared.global [%0], [%1], 16;" :: "r"(dst), "l"(src));
}
__device__ __forceinline__ void ldsm4(uint32_t* r, uint32_t a) {
    asm volatile("ldmatrix.sync.aligned.m8n8.x4.shared.b16 {%0,%1,%2,%3}, [%4];"
                 : "=r"(r[0]), "=r"(r[1]), "=r"(r[2]), "=r"(r[3]) : "r"(a));
}
__device__ __forceinline__ uint32_t f4_to_e4m3x4(float x, float y, float z, float w) {
    uint32_t pk;
    asm("{ .reg .b16 lo, hi;\n"
        "cvt.rn.satfinite.e4m3x2.f32 lo, %2, %1;\n"
        "cvt.rn.satfinite.e4m3x2.f32 hi, %4, %3;\n"
        "mov.b32 %0, {lo, hi}; }"
        : "=r"(pk) : "f"(x), "f"(y), "f"(z), "f"(w));
    return pk;
}

// ---------------------------------------------------------------------------
// Kernel 1 (fused): X normalize -> fp8, fp32-exact target cosine, acc reset
// ---------------------------------------------------------------------------
__global__ void k_prep(const float* __restrict__ X, const float* __restrict__ E,
                       const int* __restrict__ T) {
    int b = blockIdx.x;
    int t = threadIdx.x; // 128 threads, 4 floats each
    if (b == 0 && t == 0) { g_acc = 0LL; g_done = 0u; }
    int tg = max(0, min(T[b], C_N - 1));
    float4 v = *(const float4*)(X + (size_t)b * D_N + 4 * t);
    float4 e = *(const float4*)(E + (size_t)tg * D_N + 4 * t);
    float ss = v.x * v.x + v.y * v.y + v.z * v.z + v.w * v.w;
    float se = e.x * e.x + e.y * e.y + e.z * e.z + e.w * e.w;
    float sx = v.x * e.x + v.y * e.y + v.z * e.z + v.w * e.w;
    __shared__ float s1[128], s2[128], s3[128];
    s1[t] = ss; s2[t] = se; s3[t] = sx;
    __syncthreads();
    for (int s = 64; s > 0; s >>= 1) {
        if (t < s) { s1[t] += s1[t + s]; s2[t] += s2[t + s]; s3[t] += s3[t + s]; }
        __syncthreads();
    }
    float inv = 1.0f / fmaxf(sqrtf(s1[0]), EPSV);
    float q = inv * XSCL;
    *(uint32_t*)(g_Xq + (size_t)b * D_N + 4 * t) =
        f4_to_e4m3x4(v.x * q, v.y * q, v.z * q, v.w * q);
    if (t == 0)
        g_t[b] = s3[0] * inv / fmaxf(sqrtf(s2[0]), EPSV);
}

// ---------------------------------------------------------------------------
// Kernel 2: fp8 m16n8k32 (f16 acc), NT=64 tiles, 32x32 warp tiles,
// 3 CTAs/SM, 4-deep cp.async ring, fixed-point deterministic finish.
// ---------------------------------------------------------------------------
__global__ __launch_bounds__(256, 3) void k_main(const float* __restrict__ E,
                                                 float* __restrict__ out) {
    extern __shared__ __align__(1024) unsigned char smem[];
    uint32_t sbase = smem_u32(smem);
    float* invn = (float*)(smem + INVN_OFF);
    float* vmsk = (float*)(smem + VM_OFF);
    int tid = threadIdx.x, lane = tid & 31, wid = tid >> 5;
    int warp_m = wid >> 1;  // 0..3 -> 32 rows each
    int warp_n = wid & 1;   // 0..1 -> 32 classes each
    int c0 = blockIdx.x * NT;

    // ---- Phase 1: E tile fp32->e4m3 + inv-norms (/16 folded) + validity ----
    {
        int cl = tid >> 2, sub = tid & 3;   // 64 classes, 4 threads each
        int gc = c0 + cl;
        bool vld = gc < C_N;
        const float4* src = (const float4*)(E + (size_t)(vld ? gc : 0) * D_N);
        float ss = 0.f;
#pragma unroll 8
        for (int i = 0; i < 32; i++) {
            int f4 = sub + 4 * i;
            float4 v = vld ? src[f4] : make_float4(0.f, 0.f, 0.f, 0.f);
            ss += v.x * v.x + v.y * v.y + v.z * v.z + v.w * v.w;
            *(uint32_t*)(smem + cl * ES_STRB + f4 * 4) =
                f4_to_e4m3x4(v.x, v.y, v.z, v.w);
        }
        ss += __shfl_xor_sync(0xffffffffu, ss, 1);
        ss += __shfl_xor_sync(0xffffffffu, ss, 2);
        if (sub == 0) {
            invn[cl] = vld ? (1.0f / (fmaxf(sqrtf(ss), EPSV) * XSCL)) : 0.f;
            vmsk[cl] = vld ? 1.f : 0.f;
        }
    }
    __syncthreads();

    // ---- fragment addresses (relative, bytes) ----
    uint32_t aRow[2];
#pragma unroll
    for (int im = 0; im < 2; im++)
        aRow[im] = (uint32_t)((warp_m * 32 + im * 16 + (lane & 15)) * XR_BYTES +
                              (lane >> 4) * 16);
    uint32_t bRow[2];
#pragma unroll
    for (int g = 0; g < 2; g++)
        bRow[g] = (uint32_t)((warp_n * 32 + g * 16 + (lane & 15)) * ES_STRB +
                             (lane >> 4) * 16);

    auto stage = [&](int s, int buf) {
        int mb = s >> 3, kc = s & 7;
        const char* src = (const char*)g_Xq + (size_t)mb * 128 * 512 + kc * 64;
        uint32_t dst = sbase + XC_OFF + buf * XC_BYTES;
#pragma unroll
        for (int j = 0; j < 2; j++) {
            int i = tid + j * 256;
            int row = i >> 2, seg = i & 3;
            cp16(dst + row * XR_BYTES + seg * 16, src + (size_t)row * 512 + seg * 16);
        }
        asm volatile("cp.async.commit_group;" ::: "memory");
    };

    uint32_t acc[2][4][2]; // f16x2 accumulators
#pragma unroll
    for (int im = 0; im < 2; im++)
#pragma unroll
        for (int in = 0; in < 4; in++) {
            acc[im][in][0] = 0u;
            acc[im][in][1] = 0u;
        }
    float local = 0.f;

    stage(0, 0);
    stage(1, 1);
    stage(2, 2);

    for (int step = 0; step < NSTEP; step++) {
        if (step >= NSTEP - 3)
            asm volatile("cp.async.wait_group 0;" ::: "memory");
        else
            asm volatile("cp.async.wait_group 2;" ::: "memory");
        __syncthreads();
        if (step < NSTEP - 3) stage(step + 3, (step + 3) & 3);

        int kc = step & 7;
        int buf = step & 3;
        uint32_t abase = sbase + XC_OFF + buf * XC_BYTES;
        uint32_t bko = sbase + (uint32_t)(kc * 64);

#pragma unroll
        for (int ks = 0; ks < 2; ks++) {  // two k32 steps per 64-k chunk
            uint32_t a[2][4], bb[2][4];
#pragma unroll
            for (int im = 0; im < 2; im++) ldsm4(a[im], abase + aRow[im] + ks * 32);
#pragma unroll
            for (int g = 0; g < 2; g++) ldsm4(bb[g], bko + bRow[g] + ks * 32);
#pragma unroll
            for (int im = 0; im < 2; im++)
#pragma unroll
                for (int in = 0; in < 4; in++)
                    asm volatile(
                        "mma.sync.aligned.m16n8k32.row.col.f16.e4m3.e4m3.f16 "
                        "{%0,%1}, {%2,%3,%4,%5}, {%6,%7}, {%0,%1};"
                        : "+r"(acc[im][in][0]), "+r"(acc[im][in][1])
                        : "r"(a[im][0]), "r"(a[im][1]), "r"(a[im][2]), "r"(a[im][3]),
                          "r"(bb[in >> 1][in & 1]), "r"(bb[in >> 1][(in & 1) + 2]));
        }

        // ---- m-block epilogue (f32, per R11) ----
        if (kc == 7) {
            int mb = step >> 3;
            int rbase = mb * 128 + warp_m * 32 + (lane >> 2);
#pragma unroll
            for (int im = 0; im < 2; im++) {
                float b0 = MARGIN - g_t[rbase + im * 16];
                float b1 = MARGIN - g_t[rbase + im * 16 + 8];
#pragma unroll
                for (int in = 0; in < 4; in++) {
                    int c = warp_n * 32 + in * 8 + (lane & 3) * 2;
                    float i0 = invn[c], i1 = invn[c + 1];
                    float v0 = vmsk[c], v1 = vmsk[c + 1];
                    __half2 h01 = *(__half2*)&acc[im][in][0];
                    __half2 h23 = *(__half2*)&acc[im][in][1];
                    float f0 = __low2float(h01), f1 = __high2float(h01);
                    float f2 = __low2float(h23), f3 = __high2float(h23);
                    local += v0 * fmaxf(0.f, fmaf(f0, i0, b0));
                    local += v1 * fmaxf(0.f, fmaf(f1, i1, b0));
                    local += v0 * fmaxf(0.f, fmaf(f2, i0, b1));
                    local += v1 * fmaxf(0.f, fmaf(f3, i1, b1));
                    acc[im][in][0] = 0u;
                    acc[im][in][1] = 0u;
                }
            }
        }
    }

    // ---- CTA reduction + deterministic fixed-point global accumulation ----
#pragma unroll
    for (int off = 16; off > 0; off >>= 1)
        local += __shfl_xor_sync(0xffffffffu, local, off);
    __shared__ float red[8];
    if (lane == 0) red[wid] = local;
    __syncthreads();
    if (tid == 0) {
        float s = 0.f;
#pragma unroll
        for (int w = 0; w < 8; w++) s += red[w];
        atomicAdd((unsigned long long*)&g_acc,
                  (unsigned long long)(long long)llrintf(s * FXS));
        __threadfence();
        unsigned int prev = atomicAdd(&g_done, 1u);
        if (prev == NTILES - 1) {
            long long total = (long long)atomicAdd((unsigned long long*)&g_acc, 0ULL);
            out[0] = (float)((double)total / (double)FXS / (double)B_N - (double)MARGIN);
        }
    }
}

// ---------------------------------------------------------------------------
extern "C" void kernel_launch(void* const* d_in, const int* in_sizes, int n_in,
                              void* d_out, int out_size) {
    const float* X = (const float*)d_in[0];   // [1024, 512] fp32
    const float* E = (const float*)d_in[1];   // [100000, 512] fp32
    const int* T = (const int*)d_in[2];       // [1024] int32
    float* out = (float*)d_out;

    cudaFuncSetAttribute(k_main, cudaFuncAttributeMaxDynamicSharedMemorySize,
                         SMEM_BYTES);

    k_prep<<<B_N, 128>>>(X, E, T);
    k_main<<<NTILES, 256, SMEM_BYTES>>>(E, out);
}